// round 8
// baseline (speedup 1.0000x reference)
#include <cuda_runtime.h>
#include <cuda_fp16.h>

// Problem constants
#define ROWS    64          // B*S
#define DIM     512         // D
#define VOCAB   32000       // V
#define INNER   31999       // V-1
#define TDEPTH  18          // T

// GEMM tiling
#define CTA_N   128
#define KT      64
#define A_STRIDE 520        // halves
#define W_STRIDE 72         // halves
#define EP_STRIDE 72        // halves
#define SMEM_ATT_H (ROWS*A_STRIDE*2)           // 66560
#define SMEM_WT    (CTA_N*W_STRIDE*2)          // 18432
#define SMEM_K1    (SMEM_ATT_H + 2*SMEM_WT)    // 103424 -> 2 CTAs/SM

// -------- device globals --------
__device__ __align__(16) __half g_tableT[(size_t)(2 * VOCAB + 256) * ROWS]; // 8.224 MB

// -------- PTX helpers --------
__device__ __forceinline__ unsigned smem_u32(const void* p) {
    return (unsigned)__cvta_generic_to_shared(p);
}
__device__ __forceinline__ void ldmx4(unsigned& r0, unsigned& r1, unsigned& r2, unsigned& r3,
                                      unsigned addr) {
    asm volatile("ldmatrix.sync.aligned.m8n8.x4.shared.b16 {%0,%1,%2,%3}, [%4];"
                 : "=r"(r0), "=r"(r1), "=r"(r2), "=r"(r3) : "r"(addr));
}
__device__ __forceinline__ void mma16816(float* d,
                                         unsigned a0, unsigned a1, unsigned a2, unsigned a3,
                                         unsigned b0, unsigned b1) {
    asm volatile("mma.sync.aligned.m16n8k16.row.col.f32.f16.f16.f32 "
                 "{%0,%1,%2,%3}, {%4,%5,%6,%7}, {%8,%9}, {%0,%1,%2,%3};"
                 : "+f"(d[0]), "+f"(d[1]), "+f"(d[2]), "+f"(d[3])
                 : "r"(a0), "r"(a1), "r"(a2), "r"(a3), "r"(b0), "r"(b1));
}
__device__ __forceinline__ void sts_v2u32(unsigned addr, unsigned a, unsigned b) {
    asm volatile("st.shared.v2.u32 [%0], {%1,%2};" :: "r"(addr), "r"(a), "r"(b));
}

// ================= K1: GEMM via mma.sync (2 CTAs/SM, 1 sync/tile) ==========
__global__ void __launch_bounds__(256, 2)
k_gemm(const float* __restrict__ att, const float* __restrict__ weight) {
    extern __shared__ char smem[];
    const unsigned att_base = smem_u32(smem);
    const unsigned wb0 = att_base + SMEM_ATT_H;
    const unsigned wb1 = wb0 + SMEM_WT;

    const int tid  = threadIdx.x;
    const int lane = tid & 31;
    const int warp = tid >> 5;
    const int wm   = warp >> 1;       // row block of 16
    const int wn   = warp & 1;        // node block of 64
    const int base = blockIdx.x * CTA_N;

    float4 st[8];
    auto load_w = [&](int kt) {
        #pragma unroll
        for (int u = 0; u < 8; u++) {
            int idx = tid + u * 256;
            int row = idx >> 4, c4 = idx & 15;
            int ng = base + row;
            if (ng < INNER)
                st[u] = *(const float4*)(weight + (size_t)ng * DIM + kt * KT + c4 * 4);
            else
                st[u] = make_float4(0.f, 0.f, 0.f, 0.f);
        }
    };
    auto store_w = [&](unsigned wb) {
        #pragma unroll
        for (int u = 0; u < 8; u++) {
            int idx = tid + u * 256;
            int row = idx >> 4, c4 = idx & 15;
            __half2 p0 = __floats2half2_rn(st[u].x, st[u].y);
            __half2 p1 = __floats2half2_rn(st[u].z, st[u].w);
            unsigned addr = wb + (unsigned)(row * W_STRIDE + c4 * 4) * 2u;
            sts_v2u32(addr, *(unsigned*)&p0, *(unsigned*)&p1);
        }
    };

    // tile 0 load first (hits DRAM earliest)
    load_w(0);

    // ---- stage att[64][512] fp32 -> fp16 smem (stride 520) ----
    #pragma unroll 4
    for (int i = tid; i < ROWS * (DIM / 4); i += 256) {
        int r = i >> 7, k4 = i & 127;
        float4 vv = *(const float4*)(att + r * DIM + k4 * 4);
        __half2 p0 = __floats2half2_rn(vv.x, vv.y);
        __half2 p1 = __floats2half2_rn(vv.z, vv.w);
        unsigned addr = att_base + (unsigned)(r * A_STRIDE + k4 * 4) * 2u;
        sts_v2u32(addr, *(unsigned*)&p0, *(unsigned*)&p1);
    }

    store_w(wb0);      // tile 0 -> buf0
    load_w(1);         // tile 1 -> st
    __syncthreads();

    float acc[8][4];
    #pragma unroll
    for (int i = 0; i < 8; i++)
        #pragma unroll
        for (int j = 0; j < 4; j++) acc[i][j] = 0.f;

    const unsigned a_off = att_base +
        (unsigned)((wm * 16 + (lane & 15)) * A_STRIDE + ((lane >> 4) << 3)) * 2u;
    const unsigned b_off =
        (unsigned)((wn * 64 + (lane & 7) + ((lane >> 4) << 3)) * W_STRIDE
                   + (((lane >> 3) & 1) << 3)) * 2u;

    const int NTILES = DIM / KT;       // 8
    #pragma unroll 1
    for (int kt = 0; kt < NTILES; kt++) {
        // compute tile kt from buf[kt%2]
        const unsigned wb = (kt & 1) ? wb1 : wb0;
        #pragma unroll
        for (int k16 = 0; k16 < 4; k16++) {
            unsigned a0, a1, a2, a3;
            ldmx4(a0, a1, a2, a3, a_off + (unsigned)((kt * KT + k16 * 16) * 2));
            #pragma unroll
            for (int nt = 0; nt < 4; nt++) {
                unsigned b0, b1, b2, b3;
                ldmx4(b0, b1, b2, b3,
                      wb + b_off + (unsigned)((nt * 16 * W_STRIDE + k16 * 16) * 2));
                mma16816(acc[2 * nt + 0], a0, a1, a2, a3, b0, b1);
                mma16816(acc[2 * nt + 1], a0, a1, a2, a3, b2, b3);
            }
        }
        // store tile kt+1 into the other buffer (its last readers finished
        // compute(kt-1), protected by the previous iteration's sync), then
        // refill the staging registers with tile kt+2.
        if (kt + 1 < NTILES) store_w((kt & 1) ? wb0 : wb1);
        if (kt + 2 < NTILES) load_w(kt + 2);
        __syncthreads();
    }

    // ---- epilogue: log-sigmoid pair -> smem transpose -> coalesced STG.128 ----
    __half* ep = (__half*)smem;
    const int r0  = wm * 16 + (lane >> 2);
    const int c0l = wn * 64 + 2 * (lane & 3);
    #pragma unroll
    for (int nt = 0; nt < 8; nt++) {
        #pragma unroll
        for (int ri = 0; ri < 2; ri++) {
            int row = r0 + ri * 8;
            #pragma unroll
            for (int ci = 0; ci < 2; ci++) {
                float x  = acc[nt][ri * 2 + ci];
                int   nl = c0l + nt * 8 + ci;          // 0..127
                float e  = __expf(-x);
                float sp = __logf(1.0f + e);           // softplus(-x)
                ep[(2 * nl + 0) * EP_STRIDE + row] = __float2half_rn(-sp);
                ep[(2 * nl + 1) * EP_STRIDE + row] = __float2half_rn(-sp - x);
            }
        }
    }
    __syncthreads();

    // copy exactly this CTA's 256 node2 x 64 rows = 2048 uint4 (32 KB)
    __half* dst = g_tableT + (size_t)(2 * base) * ROWS;
    #pragma unroll 4
    for (int i = tid; i < 2048; i += 256) {
        int n2 = i >> 3, g = i & 7;
        uint4 q = *(const uint4*)(ep + n2 * EP_STRIDE + g * 8);
        *(uint4*)(dst + n2 * ROWS + g * 8) = q;
    }
}

// ================= K2: fused offsets + gather =================
__global__ void __launch_bounds__(256)
k_gather(const int* __restrict__ pidx, const float* __restrict__ pbias,
         float* __restrict__ out) {
    __shared__ __align__(16) unsigned soff[64 * TDEPTH];   // 4.6 KB
    __shared__ __align__(16) float stage[ROWS * 66];       // 16.9 KB

    const int tid   = threadIdx.x;
    const int lane  = tid & 31;
    const int w     = tid >> 5;
    const int hw    = lane >> 4;
    const int l15   = lane & 15;
    const int vbase = blockIdx.x * 64;
    const char* tb  = (const char*)g_tableT;

    // ---- phase 1: idx -> soff (idx<<8), coalesced ----
    const bool is64 = (pidx[1] == 0) && (pidx[3] == 0) && (pidx[65] == 0);
    const int  J    = 64 * TDEPTH;                 // 1152 elements
    if (is64) {
        const uint4* src = (const uint4*)(pidx + (size_t)vbase * TDEPTH * 2);
        #pragma unroll
        for (int i = tid; i < J / 2; i += 256) {
            uint4 u = src[i];
            soff[2 * i + 0] = u.x << 8;
            soff[2 * i + 1] = u.z << 8;
        }
    } else {
        const uint4* src = (const uint4*)(pidx + (size_t)vbase * TDEPTH);
        #pragma unroll
        for (int i = tid; i < J / 4; i += 256) {
            uint4 u = src[i];
            soff[4 * i + 0] = u.x << 8;
            soff[4 * i + 1] = u.y << 8;
            soff[4 * i + 2] = u.z << 8;
            soff[4 * i + 3] = u.w << 8;
        }
    }
    __syncthreads();

    // ---- phase 2: OR in the branch bit (bit<<7), coalesced ----
    {
        const float4* src = (const float4*)(pbias + (size_t)vbase * TDEPTH);
        #pragma unroll
        for (int i = tid; i < J / 4; i += 256) {
            float4 b = src[i];
            if (b.x > 0.5f) soff[4 * i + 0] |= 128u;
            if (b.y > 0.5f) soff[4 * i + 1] |= 128u;
            if (b.z > 0.5f) soff[4 * i + 2] |= 128u;
            if (b.w > 0.5f) soff[4 * i + 3] |= 128u;
        }
    }
    __syncthreads();

    // ---- gather: per half-warp one v, lane covers 4 rows via 8B loads ----
    #pragma unroll 2
    for (int p = 0; p < 4; p++) {
        const int vl = w * 8 + p * 2 + hw;
        float4 a = make_float4(0.f, 0.f, 0.f, 0.f);
        #pragma unroll
        for (int t = 0; t < TDEPTH; t++) {
            unsigned ob = soff[vl * TDEPTH + t];           // LDS broadcast
            uint2 q = *(const uint2*)(tb + ob + (l15 << 3));
            float2 f0 = __half22float2(*(__half2*)&q.x);
            float2 f1 = __half22float2(*(__half2*)&q.y);
            a.x += f0.x; a.y += f0.y; a.z += f1.x; a.w += f1.y;
        }
        const int r = 4 * l15;
        stage[(r + 0) * 66 + vl] = a.x;
        stage[(r + 1) * 66 + vl] = a.y;
        stage[(r + 2) * 66 + vl] = a.z;
        stage[(r + 3) * 66 + vl] = a.w;
    }
    __syncthreads();

    #pragma unroll
    for (int rr = 0; rr < 8; rr++) {
        const int r = w + rr * 8;
        float2 f = *(const float2*)&stage[r * 66 + 2 * lane];
        *(float2*)(out + (size_t)r * VOCAB + vbase + 2 * lane) = f;
    }
}

// ================= launch =================
extern "C" void kernel_launch(void* const* d_in, const int* in_sizes, int n_in,
                              void* d_out, int out_size) {
    const float* att    = (const float*)d_in[0];
    const float* weight = (const float*)d_in[1];
    const int*   pidx   = (const int*)d_in[2];   // int32 or int64 (auto-detected)
    const float* pbias  = (const float*)d_in[4];
    float* out = (float*)d_out;

    cudaFuncSetAttribute(k_gemm, cudaFuncAttributeMaxDynamicSharedMemorySize, SMEM_K1);

    k_gemm<<<VOCAB / CTA_N, 256, SMEM_K1>>>(att, weight);   // 250 CTAs, 2/SM
    k_gather<<<VOCAB / 64, 256>>>(pidx, pbias, out);        // 500 CTAs
}

// round 10
// speedup vs baseline: 1.0328x; 1.0328x over previous
#include <cuda_runtime.h>
#include <cuda_fp16.h>

// Problem constants
#define ROWS    64          // B*S
#define DIM     512         // D
#define VOCAB   32000       // V
#define INNER   31999       // V-1
#define TDEPTH  18          // T

// GEMM tiling
#define CTA_N   128
#define KT      64
#define A_STRIDE 520        // halves
#define W_STRIDE 72         // halves
#define EP_STRIDE 72        // halves
#define SMEM_ATT_H (ROWS*A_STRIDE*2)           // 66560
#define SMEM_WT    (CTA_N*W_STRIDE*2)          // 18432
#define SMEM_K1    (SMEM_ATT_H + 2*SMEM_WT)    // 103424 -> 2 CTAs/SM

// Gather tiling
#define GV      128         // vocab entries per gather CTA
#define GTHREADS 512
#define GSTRIDE 130         // padded float stride for stage (float2-aligned)

// -------- device globals --------
__device__ __align__(16) __half g_tableT[(size_t)(2 * VOCAB + 256) * ROWS]; // 8.224 MB

// -------- PTX helpers --------
__device__ __forceinline__ unsigned smem_u32(const void* p) {
    return (unsigned)__cvta_generic_to_shared(p);
}
__device__ __forceinline__ void ldmx4(unsigned& r0, unsigned& r1, unsigned& r2, unsigned& r3,
                                      unsigned addr) {
    asm volatile("ldmatrix.sync.aligned.m8n8.x4.shared.b16 {%0,%1,%2,%3}, [%4];"
                 : "=r"(r0), "=r"(r1), "=r"(r2), "=r"(r3) : "r"(addr));
}
__device__ __forceinline__ void mma16816(float* d,
                                         unsigned a0, unsigned a1, unsigned a2, unsigned a3,
                                         unsigned b0, unsigned b1) {
    asm volatile("mma.sync.aligned.m16n8k16.row.col.f32.f16.f16.f32 "
                 "{%0,%1,%2,%3}, {%4,%5,%6,%7}, {%8,%9}, {%0,%1,%2,%3};"
                 : "+f"(d[0]), "+f"(d[1]), "+f"(d[2]), "+f"(d[3])
                 : "r"(a0), "r"(a1), "r"(a2), "r"(a3), "r"(b0), "r"(b1));
}
__device__ __forceinline__ void sts_v2u32(unsigned addr, unsigned a, unsigned b) {
    asm volatile("st.shared.v2.u32 [%0], {%1,%2};" :: "r"(addr), "r"(a), "r"(b));
}

// ================= K1: GEMM via mma.sync (2 CTAs/SM) — proven R7 form =======
__global__ void __launch_bounds__(256, 2)
k_gemm(const float* __restrict__ att, const float* __restrict__ weight) {
    extern __shared__ char smem[];
    const unsigned att_base = smem_u32(smem);
    const unsigned wb0 = att_base + SMEM_ATT_H;
    const unsigned wb1 = wb0 + SMEM_WT;

    const int tid  = threadIdx.x;
    const int lane = tid & 31;
    const int warp = tid >> 5;
    const int wm   = warp >> 1;       // row block of 16
    const int wn   = warp & 1;        // node block of 64
    const int base = blockIdx.x * CTA_N;

    // ---- stage att[64][512] fp32 -> fp16 smem (stride 520) ----
    #pragma unroll 4
    for (int i = tid; i < ROWS * (DIM / 4); i += 256) {
        int r = i >> 7, k4 = i & 127;
        float4 vv = *(const float4*)(att + r * DIM + k4 * 4);
        __half2 p0 = __floats2half2_rn(vv.x, vv.y);
        __half2 p1 = __floats2half2_rn(vv.z, vv.w);
        unsigned addr = att_base + (unsigned)(r * A_STRIDE + k4 * 4) * 2u;
        sts_v2u32(addr, *(unsigned*)&p0, *(unsigned*)&p1);
    }

    float4 st[8];
    auto load_w = [&](int kt) {
        #pragma unroll
        for (int u = 0; u < 8; u++) {
            int idx = tid + u * 256;
            int row = idx >> 4, c4 = idx & 15;
            int ng = base + row;
            if (ng < INNER)
                st[u] = *(const float4*)(weight + (size_t)ng * DIM + kt * KT + c4 * 4);
            else
                st[u] = make_float4(0.f, 0.f, 0.f, 0.f);
        }
    };
    auto store_w = [&](unsigned wb) {
        #pragma unroll
        for (int u = 0; u < 8; u++) {
            int idx = tid + u * 256;
            int row = idx >> 4, c4 = idx & 15;
            __half2 p0 = __floats2half2_rn(st[u].x, st[u].y);
            __half2 p1 = __floats2half2_rn(st[u].z, st[u].w);
            unsigned addr = wb + (unsigned)(row * W_STRIDE + c4 * 4) * 2u;
            sts_v2u32(addr, *(unsigned*)&p0, *(unsigned*)&p1);
        }
    };

    float acc[8][4];
    #pragma unroll
    for (int i = 0; i < 8; i++)
        #pragma unroll
        for (int j = 0; j < 4; j++) acc[i][j] = 0.f;

    const unsigned a_off = att_base +
        (unsigned)((wm * 16 + (lane & 15)) * A_STRIDE + ((lane >> 4) << 3)) * 2u;
    const unsigned b_off =
        (unsigned)((wn * 64 + (lane & 7) + ((lane >> 4) << 3)) * W_STRIDE
                   + (((lane >> 3) & 1) << 3)) * 2u;

    load_w(0);
    store_w(wb0);
    __syncthreads();

    const int NTILES = DIM / KT;       // 8
    #pragma unroll 1
    for (int kt = 0; kt < NTILES; kt++) {
        if (kt + 1 < NTILES) load_w(kt + 1);   // dist-1 register prefetch
        const unsigned wb = (kt & 1) ? wb1 : wb0;
        #pragma unroll
        for (int k16 = 0; k16 < 4; k16++) {
            unsigned a0, a1, a2, a3;
            ldmx4(a0, a1, a2, a3, a_off + (unsigned)((kt * KT + k16 * 16) * 2));
            #pragma unroll
            for (int nt = 0; nt < 4; nt++) {
                unsigned b0, b1, b2, b3;
                ldmx4(b0, b1, b2, b3,
                      wb + b_off + (unsigned)((nt * 16 * W_STRIDE + k16 * 16) * 2));
                mma16816(acc[2 * nt + 0], a0, a1, a2, a3, b0, b1);
                mma16816(acc[2 * nt + 1], a0, a1, a2, a3, b2, b3);
            }
        }
        __syncthreads();
        if (kt + 1 < NTILES) {
            store_w((kt & 1) ? wb0 : wb1);
            __syncthreads();
        }
    }

    // ---- epilogue: log-sigmoid pair -> smem transpose -> coalesced STG.128 ----
    __half* ep = (__half*)smem;
    const int r0  = wm * 16 + (lane >> 2);
    const int c0l = wn * 64 + 2 * (lane & 3);
    __syncthreads();   // everyone done reading att smem before overwrite
    #pragma unroll
    for (int nt = 0; nt < 8; nt++) {
        #pragma unroll
        for (int ri = 0; ri < 2; ri++) {
            int row = r0 + ri * 8;
            #pragma unroll
            for (int ci = 0; ci < 2; ci++) {
                float x  = acc[nt][ri * 2 + ci];
                int   nl = c0l + nt * 8 + ci;          // 0..127
                float e  = __expf(-x);
                float sp = __logf(1.0f + e);           // softplus(-x)
                ep[(2 * nl + 0) * EP_STRIDE + row] = __float2half_rn(-sp);
                ep[(2 * nl + 1) * EP_STRIDE + row] = __float2half_rn(-sp - x);
            }
        }
    }
    __syncthreads();

    // copy exactly this CTA's 256 node2 x 64 rows = 2048 uint4 (32 KB)
    __half* dst = g_tableT + (size_t)(2 * base) * ROWS;
    #pragma unroll 4
    for (int i = tid; i < 2048; i += 256) {
        int n2 = i >> 3, g = i & 7;
        uint4 q = *(const uint4*)(ep + n2 * EP_STRIDE + g * 8);
        *(uint4*)(dst + n2 * ROWS + g * 8) = q;
    }
}

// ================= K2: fused offsets + gather, 512 thr x 128 v (1 wave) =====
__global__ void __launch_bounds__(GTHREADS)
k_gather(const int* __restrict__ pidx, const float* __restrict__ pbias,
         float* __restrict__ out) {
    __shared__ __align__(16) unsigned soff[GV * TDEPTH];     // 9.2 KB
    __shared__ __align__(16) float stage[ROWS * GSTRIDE];    // 33.3 KB

    const int tid   = threadIdx.x;
    const int lane  = tid & 31;
    const int w     = tid >> 5;          // 16 warps
    const int hw    = lane >> 4;
    const int l15   = lane & 15;
    const int vbase = blockIdx.x * GV;
    const char* tb  = (const char*)g_tableT;

    // ---- phase 1: idx -> soff (idx<<8), coalesced ----
    const bool is64 = (pidx[1] == 0) && (pidx[3] == 0) && (pidx[65] == 0);
    const int  J    = GV * TDEPTH;                 // 2304 elements
    if (is64) {
        const uint4* src = (const uint4*)(pidx + (size_t)vbase * TDEPTH * 2);
        #pragma unroll
        for (int i = tid; i < J / 2; i += GTHREADS) {
            uint4 u = src[i];
            soff[2 * i + 0] = u.x << 8;
            soff[2 * i + 1] = u.z << 8;
        }
    } else {
        const uint4* src = (const uint4*)(pidx + (size_t)vbase * TDEPTH);
        #pragma unroll
        for (int i = tid; i < J / 4; i += GTHREADS) {
            uint4 u = src[i];
            soff[4 * i + 0] = u.x << 8;
            soff[4 * i + 1] = u.y << 8;
            soff[4 * i + 2] = u.z << 8;
            soff[4 * i + 3] = u.w << 8;
        }
    }
    __syncthreads();

    // ---- phase 2: OR in the branch bit (bit<<7), coalesced ----
    {
        const float4* src = (const float4*)(pbias + (size_t)vbase * TDEPTH);
        #pragma unroll
        for (int i = tid; i < J / 4; i += GTHREADS) {
            float4 b = src[i];
            if (b.x > 0.5f) soff[4 * i + 0] |= 128u;
            if (b.y > 0.5f) soff[4 * i + 1] |= 128u;
            if (b.z > 0.5f) soff[4 * i + 2] |= 128u;
            if (b.w > 0.5f) soff[4 * i + 3] |= 128u;
        }
    }
    __syncthreads();

    // ---- gather: half-warp per v, lane covers 4 rows via 8B loads ----
    #pragma unroll 2
    for (int p = 0; p < 4; p++) {
        const int vl = w * 8 + p * 2 + hw;
        float4 a = make_float4(0.f, 0.f, 0.f, 0.f);
        #pragma unroll
        for (int t = 0; t < TDEPTH; t++) {
            unsigned ob = soff[vl * TDEPTH + t];           // LDS broadcast
            uint2 q = *(const uint2*)(tb + ob + (l15 << 3));
            float2 f0 = __half22float2(*(__half2*)&q.x);
            float2 f1 = __half22float2(*(__half2*)&q.y);
            a.x += f0.x; a.y += f0.y; a.z += f1.x; a.w += f1.y;
        }
        const int r = 4 * l15;
        stage[(r + 0) * GSTRIDE + vl] = a.x;
        stage[(r + 1) * GSTRIDE + vl] = a.y;
        stage[(r + 2) * GSTRIDE + vl] = a.z;
        stage[(r + 3) * GSTRIDE + vl] = a.w;
    }
    __syncthreads();

    // ---- writeback: warp w -> rows {w, w+16, w+32, w+48}; float2, 8B-aligned
    #pragma unroll
    for (int rr = 0; rr < 4; rr++) {
        const int r = w + rr * 16;
        float2 f0 = *(const float2*)&stage[r * GSTRIDE + 2 * lane];        // v 0..63
        float2 f1 = *(const float2*)&stage[r * GSTRIDE + 64 + 2 * lane];   // v 64..127
        *(float2*)(out + (size_t)r * VOCAB + vbase + 2 * lane)      = f0;
        *(float2*)(out + (size_t)r * VOCAB + vbase + 64 + 2 * lane) = f1;
    }
}

// ================= launch =================
extern "C" void kernel_launch(void* const* d_in, const int* in_sizes, int n_in,
                              void* d_out, int out_size) {
    const float* att    = (const float*)d_in[0];
    const float* weight = (const float*)d_in[1];
    const int*   pidx   = (const int*)d_in[2];   // int32 or int64 (auto-detected)
    const float* pbias  = (const float*)d_in[4];
    float* out = (float*)d_out;

    cudaFuncSetAttribute(k_gemm, cudaFuncAttributeMaxDynamicSharedMemorySize, SMEM_K1);

    k_gemm<<<VOCAB / CTA_N, 256, SMEM_K1>>>(att, weight);    // 250 CTAs, 2/SM
    k_gather<<<VOCAB / GV, GTHREADS>>>(pidx, pbias, out);    // 250 CTAs, 1 wave
}